// round 8
// baseline (speedup 1.0000x reference)
#include <cuda_runtime.h>
#include <cuda_bf16.h>
#include <cstdint>

// ============================================================================
// scores[b,l] = sum_d tanh( (enc[b,l,:] @ W1_e)[d] + dec_proj[b,d] + b1[d] ) * w2[d]
// out = softmax(scores, axis=-1).  B=32, LIN=2048, E=D=512, nd=1024.
//
// R8: single fused GEMM kernel. Phase 1 streams fp32 enc from DRAM and
// converts ONCE into a persistent 128KB bf16 smem tile (A16). Phase 2 runs
// 2 n-passes x 8 k-tiles of m16n8k16 bf16 MMA with warp tile 64x64
// (LDSM-balanced), B double-buffered. Scores written directly.
// ============================================================================

__device__ __align__(16) __nv_bfloat16 g_W1Tb[512 * 512];  // W1_e^T bf16 [d][k]
__device__ __align__(16) float g_dpp[512 * 512];           // dec_proj partials [b*16+kc][d]
__device__ __align__(16) float g_scores[32 * 2048];        // pre-softmax scores

// ---------------------------------------------------------------------------
// helpers
// ---------------------------------------------------------------------------
__device__ __forceinline__ uint32_t smem_u32(const void* p) {
    uint32_t a;
    asm("{ .reg .u64 t; cvta.to.shared.u64 t, %1; cvt.u32.u64 %0, t; }" : "=r"(a) : "l"(p));
    return a;
}
__device__ __forceinline__ void cp_async16(uint32_t sdst, const void* gsrc) {
    asm volatile("cp.async.cg.shared.global [%0], [%1], 16;" :: "r"(sdst), "l"(gsrc) : "memory");
}
#define CP_COMMIT() asm volatile("cp.async.commit_group;" ::: "memory")
#define CP_WAIT(n)  asm volatile("cp.async.wait_group %0;" :: "n"(n) : "memory")

__device__ __forceinline__ float tanh_fast(float x) {
    float t;
    asm("tanh.approx.f32 %0, %1;" : "=f"(t) : "f"(x));
    return t;
}
__device__ __forceinline__ void ldmatrix_x4(uint32_t r[4], uint32_t addr) {
    asm volatile("ldmatrix.sync.aligned.m8n8.x4.shared.b16 {%0,%1,%2,%3}, [%4];"
                 : "=r"(r[0]), "=r"(r[1]), "=r"(r[2]), "=r"(r[3]) : "r"(addr));
}
__device__ __forceinline__ void mma_bf16(float c[4], const uint32_t a[4], const uint32_t b[2]) {
    asm volatile(
        "mma.sync.aligned.m16n8k16.row.col.f32.bf16.bf16.f32 "
        "{%0,%1,%2,%3}, {%4,%5,%6,%7}, {%8,%9}, {%0,%1,%2,%3};"
        : "+f"(c[0]), "+f"(c[1]), "+f"(c[2]), "+f"(c[3])
        : "r"(a[0]), "r"(a[1]), "r"(a[2]), "r"(a[3]), "r"(b[0]), "r"(b[1]));
}

// ---------------------------------------------------------------------------
// Kernel P: prep. [0,512): dec_proj partials (b x 16 k-chunks of 64);
//           [512,768): W1_e^T -> bf16.
// ---------------------------------------------------------------------------
__global__ void __launch_bounds__(256) prep_kernel(
    const float* __restrict__ W1, const float* __restrict__ dh) {
    int bid = blockIdx.x, tid = threadIdx.x;
    if (bid >= 512) {
        __shared__ float tile[32][33];
        int v = bid - 512;
        int d0 = (v & 15) * 32, k0 = (v >> 4) * 32;
        int tx = tid & 31, ty = tid >> 5;
#pragma unroll
        for (int j = 0; j < 32; j += 8)
            tile[ty + j][tx] = W1[(size_t)(1024 + k0 + ty + j) * 512 + d0 + tx];
        __syncthreads();
#pragma unroll
        for (int j = 0; j < 32; j += 8)
            g_W1Tb[(size_t)(d0 + ty + j) * 512 + k0 + tx] = __float2bfloat16_rn(tile[tx][ty + j]);
    } else {
        // dec_proj partial: block = b*16 + kc, k range [kc*64, kc*64+64)
        __shared__ float sdf[64];
        int b = bid >> 4, kc = bid & 15;
        int k0 = kc * 64;
        if (tid < 64) sdf[tid] = dh[b * 1024 + k0 + tid];
        __syncthreads();
        const float* w0 = W1 + (size_t)k0 * 512 + tid;        // W1_d rows
        const float* w1 = w0 + 256;
        float a[8] = {0.f, 0.f, 0.f, 0.f, 0.f, 0.f, 0.f, 0.f};
#pragma unroll 4
        for (int k = 0; k < 64; k += 2) {
            a[0] = fmaf(sdf[k],     w0[(size_t)k * 512],       a[0]);
            a[1] = fmaf(sdf[k + 1], w0[(size_t)(k + 1) * 512], a[1]);
            a[2] = fmaf(sdf[k],     w1[(size_t)k * 512],       a[2]);
            a[3] = fmaf(sdf[k + 1], w1[(size_t)(k + 1) * 512], a[3]);
        }
        g_dpp[(size_t)bid * 512 + tid]       = a[0] + a[1];
        g_dpp[(size_t)bid * 512 + tid + 256] = a[2] + a[3];
    }
}

// ---------------------------------------------------------------------------
// Kernel M: fused convert + bf16 GEMM + tanh + dot(w2).
// Grid 512 CTAs (one per 128-row chunk), 256 thr, occ 1.
// smem: aux 8KB | A16 persistent 128KB (8 blocks of 16KB) | B 2x32KB
//       (B buffers double as fp32-A staging during phase 1).
// Warp grid 2m x 4n, warp tile 64x64 (acc 128 regs). 2 n-passes x 8 k-tiles.
// ---------------------------------------------------------------------------
static constexpr uint32_t OFF_ADD  = 0;       // 512 f
static constexpr uint32_t OFF_W2   = 2048;    // 512 f
static constexpr uint32_t OFF_PART = 4096;    // 512 f
static constexpr uint32_t OFF_SSUM = 6144;    // 128 f
static constexpr uint32_t OFF_A16  = 8192;    // 128 KB
static constexpr uint32_t OFF_B    = OFF_A16 + 131072;  // 2 x 32 KB
static constexpr uint32_t SMEM_MAIN = OFF_B + 65536;    // 204800 (200 KB)

__global__ void __launch_bounds__(256, 1)
attn_main_kernel(const float* __restrict__ enc, const float* __restrict__ b1,
                 const float* __restrict__ w2) {
    extern __shared__ char sm[];
    float* add_s = (float*)(sm + OFF_ADD);
    float* w2_s  = (float*)(sm + OFF_W2);
    float* spart = (float*)(sm + OFF_PART);
    float* ssum  = (float*)(sm + OFF_SSUM);
    const uint32_t smu  = smem_u32(sm);
    const uint32_t a16u = smu + OFF_A16;
    const uint32_t bu   = smu + OFF_B;

    const int tid  = threadIdx.x;
    const int lane = tid & 31, wid = tid >> 5;
    const int wm   = wid & 1, wn = wid >> 1;       // 2m x 4n
    const int quad = lane >> 2, qlane = lane & 3;
    const int lane7 = lane & 7;

    const int rc = blockIdx.x;                     // 0..511
    const size_t row0 = (size_t)rc * 128;
    const float* gA = enc + row0 * 512;
    const int b = rc >> 4;

    // ---- phase 1: stream fp32 A, convert to persistent A16 ----
    // staging chunk c: 128 rows x 64 fp32 = 32KB at bu + (c&1)*32768
    auto prefetchA = [&](int c) {
        uint32_t dst = bu + (uint32_t)(c & 1) * 32768;
        const float* src = gA + c * 64;
#pragma unroll
        for (int p = 0; p < 8; p++) {
            int slot = tid + p * 256;
            int r = slot >> 4, cc = slot & 15;
            cp_async16(dst + (uint32_t)slot * 16, src + (size_t)r * 512 + cc * 4);
        }
        CP_COMMIT();
    };

    prefetchA(0);

    // dec_proj reduce + b1 + w2 into smem (overlaps A stream)
    for (int d = tid; d < 512; d += 256) {
        float s = b1[d];
#pragma unroll
        for (int kc = 0; kc < 16; kc++)
            s += g_dpp[(size_t)(b * 16 + kc) * 512 + d];
        add_s[d] = s;
        w2_s[d] = w2[d];
    }
    if (tid < 128) ssum[tid] = 0.f;

    const int cv_r0 = tid >> 4, cv_c = tid & 15;
    for (int c = 0; c < 8; c++) {
        CP_WAIT(0);
        __syncthreads();
        if (c < 7) prefetchA(c + 1);
        const char* stg = sm + OFF_B + (uint32_t)(c & 1) * 32768;
        char* dst = sm + OFF_A16 + (uint32_t)c * 16384;
#pragma unroll
        for (int p = 0; p < 8; p++) {
            int r = cv_r0 + p * 16;
            float4 v = *(const float4*)(stg + (uint32_t)(r * 256 + cv_c * 16));
            __nv_bfloat162 q0 = __float22bfloat162_rn({v.x, v.y});
            __nv_bfloat162 q1 = __float22bfloat162_rn({v.z, v.w});
            uint2 o;
            o.x = *(uint32_t*)&q0; o.y = *(uint32_t*)&q1;
            uint32_t off = (uint32_t)(r * 128 + (((cv_c >> 1) ^ (r & 7)) << 4) + (cv_c & 1) * 8);
            *(uint2*)(dst + off) = o;
        }
        __syncthreads();   // staging (c&1) free for refill; A16 block c done
    }

    // ---- phase 2: 2 n-passes x 8 k-tiles, B double-buffered ----
    // B tile t (= pass*8+kt): 256 d-rows x 64 k bf16 = 32KB at bu + (t&1)*32768
    auto prefetchB = [&](int t) {
        uint32_t dst = bu + (uint32_t)(t & 1) * 32768;
        const __nv_bfloat16* src = g_W1Tb + (size_t)((t >> 3) * 256) * 512 + (t & 7) * 64;
#pragma unroll
        for (int p = 0; p < 8; p++) {
            int slot = tid + p * 256;
            int r = slot >> 3, blk = slot & 7;
            cp_async16(dst + (uint32_t)(r * 128 + ((blk ^ (r & 7)) << 4)),
                       src + (size_t)r * 512 + blk * 8);
        }
        CP_COMMIT();
    };

    prefetchB(0);

    float acc[4][8][4];
#pragma unroll
    for (int mf = 0; mf < 4; mf++)
#pragma unroll
        for (int nf = 0; nf < 8; nf++)
#pragma unroll
            for (int k = 0; k < 4; k++) acc[mf][nf][k] = 0.f;

    const uint32_t a_row = (uint32_t)(wm * 64 + ((lane >> 3) & 1) * 8 + lane7);
    const uint32_t b_row = (uint32_t)(wn * 64 + (lane >> 4) * 8 + lane7);

#pragma unroll 1
    for (int t = 0; t < 16; t++) {
        CP_WAIT(0);
        __syncthreads();
        if (t + 1 < 16) prefetchB(t + 1);

        uint32_t sA = a16u + (uint32_t)(t & 7) * 16384;
        uint32_t sB = bu + (uint32_t)(t & 1) * 32768;

#pragma unroll
        for (int kf = 0; kf < 4; kf++) {
            uint32_t afr[4][4], bfr[8][2];
            uint32_t ablk = (uint32_t)(((kf * 2 + (lane >> 4)) ^ lane7) << 4);
            uint32_t bblk = (uint32_t)(((kf * 2 + ((lane >> 3) & 1)) ^ lane7) << 4);
#pragma unroll
            for (int mf = 0; mf < 4; mf++)
                ldmatrix_x4(afr[mf], sA + (a_row + mf * 16) * 128 + ablk);
#pragma unroll
            for (int j = 0; j < 4; j++) {
                uint32_t r[4];
                ldmatrix_x4(r, sB + (b_row + j * 16) * 128 + bblk);
                bfr[2 * j][0] = r[0];     bfr[2 * j][1] = r[1];
                bfr[2 * j + 1][0] = r[2]; bfr[2 * j + 1][1] = r[3];
            }
#pragma unroll
            for (int mf = 0; mf < 4; mf++)
#pragma unroll
                for (int nf = 0; nf < 8; nf++)
                    mma_bf16(acc[mf][nf], afr[mf], bfr[nf]);
        }

        if ((t & 7) == 7) {
            // ---- epilogue for n-pass (t>>3): tanh(acc+add)*w2, row-reduce ----
            int pass = t >> 3;
#pragma unroll
            for (int mf = 0; mf < 4; mf++) {
                float s0 = 0.f, s1 = 0.f;
#pragma unroll
                for (int nf = 0; nf < 8; nf++) {
                    int c = pass * 256 + wn * 64 + nf * 8 + qlane * 2;
                    float a0 = add_s[c], a1 = add_s[c + 1];
                    float v0 = w2_s[c],  v1 = w2_s[c + 1];
                    s0 = fmaf(tanh_fast(acc[mf][nf][0] + a0), v0, s0);
                    s0 = fmaf(tanh_fast(acc[mf][nf][1] + a1), v1, s0);
                    s1 = fmaf(tanh_fast(acc[mf][nf][2] + a0), v0, s1);
                    s1 = fmaf(tanh_fast(acc[mf][nf][3] + a1), v1, s1);
                    acc[mf][nf][0] = 0.f; acc[mf][nf][1] = 0.f;
                    acc[mf][nf][2] = 0.f; acc[mf][nf][3] = 0.f;
                }
                s0 += __shfl_xor_sync(0xffffffffu, s0, 1);
                s0 += __shfl_xor_sync(0xffffffffu, s0, 2);
                s1 += __shfl_xor_sync(0xffffffffu, s1, 1);
                s1 += __shfl_xor_sync(0xffffffffu, s1, 2);
                if (qlane == 0) {
                    int r = wm * 64 + mf * 16 + quad;
                    spart[wn * 128 + r]     = s0;
                    spart[wn * 128 + r + 8] = s1;
                }
            }
            __syncthreads();
            if (tid < 128)
                ssum[tid] += spart[tid] + spart[128 + tid] + spart[256 + tid] + spart[384 + tid];
            __syncthreads();
        }
    }

    if (tid < 128) g_scores[row0 + tid] = ssum[tid];
}

// ---------------------------------------------------------------------------
// Kernel S: row softmax over 2048. 32 blocks x 256 threads.
// ---------------------------------------------------------------------------
__global__ void softmax_kernel(float* __restrict__ out) {
    __shared__ float red[256];
    int b = blockIdx.x, t = threadIdx.x;
    float v[8];
    float vmax = -1e30f;
#pragma unroll
    for (int j = 0; j < 8; j++) {
        v[j] = g_scores[(size_t)b * 2048 + j * 256 + t];
        vmax = fmaxf(vmax, v[j]);
    }
    red[t] = vmax; __syncthreads();
    for (int s = 128; s > 0; s >>= 1) {
        if (t < s) red[t] = fmaxf(red[t], red[t + s]);
        __syncthreads();
    }
    vmax = red[0]; __syncthreads();
    float sum = 0.f;
#pragma unroll
    for (int j = 0; j < 8; j++) {
        v[j] = __expf(v[j] - vmax);
        sum += v[j];
    }
    red[t] = sum; __syncthreads();
    for (int s = 128; s > 0; s >>= 1) {
        if (t < s) red[t] += red[t + s];
        __syncthreads();
    }
    float inv = 1.0f / red[0];
#pragma unroll
    for (int j = 0; j < 8; j++)
        out[b * 2048 + j * 256 + t] = v[j] * inv;
}

// ---------------------------------------------------------------------------
// kernel_launch — inputs: d_hidden, encoder_outputs, W1, b1, w2
// ---------------------------------------------------------------------------
extern "C" void kernel_launch(void* const* d_in, const int* in_sizes, int n_in,
                              void* d_out, int out_size) {
    const float* dh  = (const float*)d_in[0];  // (32, 2, 512)
    const float* enc = (const float*)d_in[1];  // (32, 2048, 512)
    const float* W1  = (const float*)d_in[2];  // (1536, 512)
    const float* b1  = (const float*)d_in[3];  // (512,)
    const float* w2  = (const float*)d_in[4];  // (512,)
    float* out = (float*)d_out;                // (32, 2048)

    cudaFuncSetAttribute(attn_main_kernel, cudaFuncAttributeMaxDynamicSharedMemorySize,
                         (int)SMEM_MAIN);

    prep_kernel<<<768, 256>>>(W1, dh);
    attn_main_kernel<<<512, 256, SMEM_MAIN>>>(enc, b1, w2);
    softmax_kernel<<<32, 256>>>(out);
}

// round 9
// speedup vs baseline: 1.4372x; 1.4372x over previous
#include <cuda_runtime.h>
#include <cuda_bf16.h>
#include <cstdint>

// ============================================================================
// scores[b,l] = sum_d tanh( (enc[b,l,:] @ W1_e)[d] + dec_proj[b,d] + b1[d] ) * w2[d]
// out = softmax(scores, axis=-1).  B=32, LIN=2048, E=D=512, nd=1024.
//
// R9: R6's occ-2 main (CTA 128x128, warp 64x32) + in-kernel A conversion:
// per k-tile, threads LDG fp32 A (L2-resident via cu-inner order), cvt in
// registers, STS bf16 into triple-buffered A16. One sync per k-tile.
// Kills the standalone 46us conversion pass. B cp.async triple-buffered.
// ============================================================================

__device__ __align__(16) __nv_bfloat16 g_W1Tb[512 * 512];  // W1_e^T bf16 [d][k]
__device__ __align__(16) float g_dpp[512 * 512];           // dec_proj partials [b*16+kc][d]
__device__ __align__(16) float g_spart[4u * 65536u];       // per-colunit partial scores

// ---------------------------------------------------------------------------
// helpers
// ---------------------------------------------------------------------------
__device__ __forceinline__ uint32_t smem_u32(const void* p) {
    uint32_t a;
    asm("{ .reg .u64 t; cvta.to.shared.u64 t, %1; cvt.u32.u64 %0, t; }" : "=r"(a) : "l"(p));
    return a;
}
__device__ __forceinline__ void cp_async16(uint32_t sdst, const void* gsrc) {
    asm volatile("cp.async.cg.shared.global [%0], [%1], 16;" :: "r"(sdst), "l"(gsrc) : "memory");
}
#define CP_COMMIT() asm volatile("cp.async.commit_group;" ::: "memory")
#define CP_WAIT(n)  asm volatile("cp.async.wait_group %0;" :: "n"(n) : "memory")

__device__ __forceinline__ float tanh_fast(float x) {
    float t;
    asm("tanh.approx.f32 %0, %1;" : "=f"(t) : "f"(x));
    return t;
}
__device__ __forceinline__ void ldmatrix_x4(uint32_t r[4], uint32_t addr) {
    asm volatile("ldmatrix.sync.aligned.m8n8.x4.shared.b16 {%0,%1,%2,%3}, [%4];"
                 : "=r"(r[0]), "=r"(r[1]), "=r"(r[2]), "=r"(r[3]) : "r"(addr));
}
__device__ __forceinline__ void mma_bf16(float c[4], const uint32_t a[4], const uint32_t b[2]) {
    asm volatile(
        "mma.sync.aligned.m16n8k16.row.col.f32.bf16.bf16.f32 "
        "{%0,%1,%2,%3}, {%4,%5,%6,%7}, {%8,%9}, {%0,%1,%2,%3};"
        : "+f"(c[0]), "+f"(c[1]), "+f"(c[2]), "+f"(c[3])
        : "r"(a[0]), "r"(a[1]), "r"(a[2]), "r"(a[3]), "r"(b[0]), "r"(b[1]));
}

// ---------------------------------------------------------------------------
// Kernel P: prep (R8 version, measured 13us).
//   [0,512): dec_proj partials (b x 16 k-chunks of 64); [512,768): W1_e^T.
// ---------------------------------------------------------------------------
__global__ void __launch_bounds__(256) prep_kernel(
    const float* __restrict__ W1, const float* __restrict__ dh) {
    int bid = blockIdx.x, tid = threadIdx.x;
    if (bid >= 512) {
        __shared__ float tile[32][33];
        int v = bid - 512;
        int d0 = (v & 15) * 32, k0 = (v >> 4) * 32;
        int tx = tid & 31, ty = tid >> 5;
#pragma unroll
        for (int j = 0; j < 32; j += 8)
            tile[ty + j][tx] = W1[(size_t)(1024 + k0 + ty + j) * 512 + d0 + tx];
        __syncthreads();
#pragma unroll
        for (int j = 0; j < 32; j += 8)
            g_W1Tb[(size_t)(d0 + ty + j) * 512 + k0 + tx] = __float2bfloat16_rn(tile[tx][ty + j]);
    } else {
        __shared__ float sdf[64];
        int b = bid >> 4, kc = bid & 15;
        int k0 = kc * 64;
        if (tid < 64) sdf[tid] = dh[b * 1024 + k0 + tid];
        __syncthreads();
        const float* w0 = W1 + (size_t)k0 * 512 + tid;
        const float* w1 = w0 + 256;
        float a[8] = {0.f, 0.f, 0.f, 0.f, 0.f, 0.f, 0.f, 0.f};
#pragma unroll 4
        for (int k = 0; k < 64; k += 2) {
            a[0] = fmaf(sdf[k],     w0[(size_t)k * 512],       a[0]);
            a[1] = fmaf(sdf[k + 1], w0[(size_t)(k + 1) * 512], a[1]);
            a[2] = fmaf(sdf[k],     w1[(size_t)k * 512],       a[2]);
            a[3] = fmaf(sdf[k + 1], w1[(size_t)(k + 1) * 512], a[3]);
        }
        g_dpp[(size_t)bid * 512 + tid]       = a[0] + a[1];
        g_dpp[(size_t)bid * 512 + tid + 256] = a[2] + a[3];
    }
}

// ---------------------------------------------------------------------------
// Kernel M: fused convert + bf16 GEMM + tanh + dot(w2).
// Grid 2048: bid = rc*4 + cu (cu inner -> fp32 A L2-resident).
// 8 warps 2m x 4n, warp tile 64x32, acc 64 regs, occ 2.
// smem: aux 4KB | A16 3x16KB | B 3x16KB = 100KB. One sync per k-tile.
// ---------------------------------------------------------------------------
static constexpr uint32_t AUX_SZ   = 4096;
static constexpr uint32_t OFF_A16  = AUX_SZ;             // 3 x 16KB
static constexpr uint32_t OFF_B    = OFF_A16 + 49152;    // 3 x 16KB
static constexpr uint32_t SMEM_MAIN = OFF_B + 49152;     // 102400 (100 KB)

__global__ void __launch_bounds__(256, 2)
attn_main_kernel(const float* __restrict__ enc, const float* __restrict__ b1,
                 const float* __restrict__ w2) {
    extern __shared__ char sm[];
    float* add_s = (float*)sm;                 // 128 f
    float* w2_s  = (float*)(sm + 512);         // 128 f
    float* spart = (float*)(sm + 1024);        // 4 x 128 f
    const uint32_t smu  = smem_u32(sm);
    const uint32_t a16u = smu + OFF_A16;
    const uint32_t bu   = smu + OFF_B;

    const int tid  = threadIdx.x;
    const int lane = tid & 31, wid = tid >> 5;
    const int wm   = wid & 1, wn = wid >> 1;   // 2m x 4n
    const int quad = lane >> 2, qlane = lane & 3;
    const int lane7 = lane & 7;

    const int cu = blockIdx.x & 3;             // column unit (inner -> L2 A reuse)
    const int rc = blockIdx.x >> 2;            // row chunk 0..511
    const size_t row0 = (size_t)rc * 128;
    const float* gA = enc + row0 * 512;
    const __nv_bfloat16* gB = g_W1Tb + (size_t)(cu * 128) * 512;
    const int b = rc >> 4;

    // B k-tile t -> buffer t%3 (128 rows x 128B, ldmatrix swizzle)
    auto prefetchB = [&](int t) {
        if (t < 8) {
            uint32_t dst = bu + (uint32_t)(t % 3) * 16384;
            const __nv_bfloat16* src = gB + t * 64;
#pragma unroll
            for (int p = 0; p < 4; p++) {
                int slot = tid + p * 256;
                int r = slot >> 3, blk = slot & 7;
                cp_async16(dst + (uint32_t)(r * 128 + ((blk ^ (r & 7)) << 4)),
                           src + (size_t)r * 512 + blk * 8);
            }
        }
        CP_COMMIT();
    };

    // A k-tile t: LDG fp32 -> cvt -> STS bf16 into A16 buffer t%3.
    // thread t: rows (tid>>4)+16p, float4-col (tid&15). Coalesced (4 lines/warp).
    const int av_r0 = tid >> 4, av_c = tid & 15;
    auto convertA = [&](int t) {
        char* dst = sm + OFF_A16 + (uint32_t)(t % 3) * 16384;
        const float* src = gA + t * 64;
        float4 v[8];
#pragma unroll
        for (int p = 0; p < 8; p++)
            v[p] = *(const float4*)(src + (size_t)(av_r0 + p * 16) * 512 + av_c * 4);
#pragma unroll
        for (int p = 0; p < 8; p++) {
            int r = av_r0 + p * 16;
            __nv_bfloat162 q0 = __float22bfloat162_rn({v[p].x, v[p].y});
            __nv_bfloat162 q1 = __float22bfloat162_rn({v[p].z, v[p].w});
            uint2 o;
            o.x = *(uint32_t*)&q0; o.y = *(uint32_t*)&q1;
            uint32_t off = (uint32_t)(r * 128 + (((av_c >> 1) ^ (r & 7)) << 4) + (av_c & 1) * 8);
            *(uint2*)(dst + off) = o;
        }
    };

    // prologue: B(0), B(1) in flight; A16(0) built.
    prefetchB(0);
    prefetchB(1);

    // add_s = sum of 16 dec_proj partials + b1; w2_s (overlaps B prefetch)
    if (tid < 128) {
        int d = cu * 128 + tid;
        float s0 = 0.f, s1 = 0.f, s2 = 0.f, s3 = 0.f;
#pragma unroll
        for (int kc = 0; kc < 16; kc += 4) {
            s0 += g_dpp[(size_t)(b * 16 + kc + 0) * 512 + d];
            s1 += g_dpp[(size_t)(b * 16 + kc + 1) * 512 + d];
            s2 += g_dpp[(size_t)(b * 16 + kc + 2) * 512 + d];
            s3 += g_dpp[(size_t)(b * 16 + kc + 3) * 512 + d];
        }
        add_s[tid] = (s0 + s1) + (s2 + s3) + b1[d];
        w2_s[tid]  = w2[d];
    }
    convertA(0);

    float acc[4][4][4];
#pragma unroll
    for (int mf = 0; mf < 4; mf++)
#pragma unroll
        for (int nf = 0; nf < 4; nf++)
#pragma unroll
            for (int k = 0; k < 4; k++) acc[mf][nf][k] = 0.f;

    const uint32_t a_row = (uint32_t)(wm * 64 + ((lane >> 3) & 1) * 8 + lane7);
    const uint32_t b_row = (uint32_t)(wn * 32 + (lane >> 4) * 8 + lane7);

#pragma unroll 1
    for (int i = 0; i < 8; i++) {
        if (i + 1 < 8) convertA(i + 1);        // STS into (i+1)%3; visible after next sync
        CP_WAIT(1);                            // B(i) complete (B(i+1) may be in flight)
        __syncthreads();                       // orders STS(A i) [prev iter] + B(i) data
        prefetchB(i + 2);                      // writes B (i+2)%3, disjoint from B i%3

        uint32_t sA = a16u + (uint32_t)(i % 3) * 16384;
        uint32_t sB = bu + (uint32_t)(i % 3) * 16384;

#pragma unroll
        for (int kf = 0; kf < 4; kf++) {
            uint32_t afr[4][4], bfr[4][2];
            uint32_t ablk = (uint32_t)(((kf * 2 + (lane >> 4)) ^ lane7) << 4);
            uint32_t bblk = (uint32_t)(((kf * 2 + ((lane >> 3) & 1)) ^ lane7) << 4);
#pragma unroll
            for (int mf = 0; mf < 4; mf++)
                ldmatrix_x4(afr[mf], sA + (a_row + mf * 16) * 128 + ablk);
#pragma unroll
            for (int j = 0; j < 2; j++) {
                uint32_t r[4];
                ldmatrix_x4(r, sB + (b_row + j * 16) * 128 + bblk);
                bfr[2 * j][0] = r[0];     bfr[2 * j][1] = r[1];
                bfr[2 * j + 1][0] = r[2]; bfr[2 * j + 1][1] = r[3];
            }
#pragma unroll
            for (int mf = 0; mf < 4; mf++)
#pragma unroll
                for (int nf = 0; nf < 4; nf++)
                    mma_bf16(acc[mf][nf], afr[mf], bfr[nf]);
        }
    }

    // ---- epilogue: tanh(acc + add) * w2, reduce over this cu's 128 cols ----
#pragma unroll
    for (int mf = 0; mf < 4; mf++) {
        float s0 = 0.f, s1 = 0.f;
#pragma unroll
        for (int nf = 0; nf < 4; nf++) {
            int c = wn * 32 + nf * 8 + qlane * 2;
            float a0 = add_s[c], a1 = add_s[c + 1];
            float v0 = w2_s[c],  v1 = w2_s[c + 1];
            s0 = fmaf(tanh_fast(acc[mf][nf][0] + a0), v0, s0);
            s0 = fmaf(tanh_fast(acc[mf][nf][1] + a1), v1, s0);
            s1 = fmaf(tanh_fast(acc[mf][nf][2] + a0), v0, s1);
            s1 = fmaf(tanh_fast(acc[mf][nf][3] + a1), v1, s1);
        }
        s0 += __shfl_xor_sync(0xffffffffu, s0, 1);
        s0 += __shfl_xor_sync(0xffffffffu, s0, 2);
        s1 += __shfl_xor_sync(0xffffffffu, s1, 1);
        s1 += __shfl_xor_sync(0xffffffffu, s1, 2);
        if (qlane == 0) {
            int r = wm * 64 + mf * 16 + quad;
            spart[wn * 128 + r]     = s0;
            spart[wn * 128 + r + 8] = s1;
        }
    }
    __syncthreads();
    if (tid < 128)
        g_spart[(size_t)cu * 65536 + row0 + tid] =
            spart[tid] + spart[128 + tid] + spart[256 + tid] + spart[384 + tid];
}

// ---------------------------------------------------------------------------
// Kernel S: sum 4 partials + row softmax over 2048. 32 blocks x 256 threads.
// ---------------------------------------------------------------------------
__global__ void softmax_kernel(float* __restrict__ out) {
    __shared__ float red[256];
    int b = blockIdx.x, t = threadIdx.x;
    float v[8];
    float vmax = -1e30f;
#pragma unroll
    for (int j = 0; j < 8; j++) {
        size_t idx = (size_t)b * 2048 + j * 256 + t;
        v[j] = g_spart[idx] + g_spart[65536 + idx] + g_spart[131072 + idx] + g_spart[196608 + idx];
        vmax = fmaxf(vmax, v[j]);
    }
    red[t] = vmax; __syncthreads();
    for (int s = 128; s > 0; s >>= 1) {
        if (t < s) red[t] = fmaxf(red[t], red[t + s]);
        __syncthreads();
    }
    vmax = red[0]; __syncthreads();
    float sum = 0.f;
#pragma unroll
    for (int j = 0; j < 8; j++) {
        v[j] = __expf(v[j] - vmax);
        sum += v[j];
    }
    red[t] = sum; __syncthreads();
    for (int s = 128; s > 0; s >>= 1) {
        if (t < s) red[t] += red[t + s];
        __syncthreads();
    }
    float inv = 1.0f / red[0];
#pragma unroll
    for (int j = 0; j < 8; j++)
        out[b * 2048 + j * 256 + t] = v[j] * inv;
}

// ---------------------------------------------------------------------------
// kernel_launch — inputs: d_hidden, encoder_outputs, W1, b1, w2
// ---------------------------------------------------------------------------
extern "C" void kernel_launch(void* const* d_in, const int* in_sizes, int n_in,
                              void* d_out, int out_size) {
    const float* dh  = (const float*)d_in[0];  // (32, 2, 512)
    const float* enc = (const float*)d_in[1];  // (32, 2048, 512)
    const float* W1  = (const float*)d_in[2];  // (1536, 512)
    const float* b1  = (const float*)d_in[3];  // (512,)
    const float* w2  = (const float*)d_in[4];  // (512,)
    float* out = (float*)d_out;                // (32, 2048)

    cudaFuncSetAttribute(attn_main_kernel, cudaFuncAttributeMaxDynamicSharedMemorySize,
                         (int)SMEM_MAIN);

    prep_kernel<<<768, 256>>>(W1, dh);
    attn_main_kernel<<<2048, 256, SMEM_MAIN>>>(enc, b1, w2);
    softmax_kernel<<<32, 256>>>(out);
}

// round 10
// speedup vs baseline: 1.6470x; 1.1460x over previous
#include <cuda_runtime.h>
#include <cuda_bf16.h>
#include <cstdint>

// ============================================================================
// scores[b,l] = sum_d tanh( (enc[b,l,:] @ W1_e)[d] + dec_proj[b,d] + b1[d] ) * w2[d]
// out = softmax(scores, axis=-1).  B=32, LIN=2048, E=D=512, nd=1024.
//
// R10: recombination of measured-best components.
//   main  = R7's staged-convert GEMM (cp.async fp32 A -> smem convert -> bf16
//           MMA, occ 2, warp 64x32)            [measured ~106us]
//   prep  = R8/R9 fine-split dec_proj + W1^T   [measured 10.7us]
//   softmax unchanged                           [~6us]
// ============================================================================

__device__ __align__(16) __nv_bfloat16 g_W1Tb[512 * 512];  // W1_e^T bf16 [d][k]
__device__ __align__(16) float g_dpp[512 * 512];           // dec_proj partials [b*16+kc][d]
__device__ __align__(16) float g_spart[4u * 65536u];       // per-colunit partial scores

// ---------------------------------------------------------------------------
// helpers
// ---------------------------------------------------------------------------
__device__ __forceinline__ uint32_t smem_u32(const void* p) {
    uint32_t a;
    asm("{ .reg .u64 t; cvta.to.shared.u64 t, %1; cvt.u32.u64 %0, t; }" : "=r"(a) : "l"(p));
    return a;
}
__device__ __forceinline__ void cp_async16(uint32_t sdst, const void* gsrc) {
    asm volatile("cp.async.cg.shared.global [%0], [%1], 16;" :: "r"(sdst), "l"(gsrc) : "memory");
}
#define CP_COMMIT() asm volatile("cp.async.commit_group;" ::: "memory")
#define CP_WAIT(n)  asm volatile("cp.async.wait_group %0;" :: "n"(n) : "memory")

__device__ __forceinline__ float tanh_fast(float x) {
    float t;
    asm("tanh.approx.f32 %0, %1;" : "=f"(t) : "f"(x));
    return t;
}
__device__ __forceinline__ void ldmatrix_x4(uint32_t r[4], uint32_t addr) {
    asm volatile("ldmatrix.sync.aligned.m8n8.x4.shared.b16 {%0,%1,%2,%3}, [%4];"
                 : "=r"(r[0]), "=r"(r[1]), "=r"(r[2]), "=r"(r[3]) : "r"(addr));
}
__device__ __forceinline__ void mma_bf16(float c[4], const uint32_t a[4], const uint32_t b[2]) {
    asm volatile(
        "mma.sync.aligned.m16n8k16.row.col.f32.bf16.bf16.f32 "
        "{%0,%1,%2,%3}, {%4,%5,%6,%7}, {%8,%9}, {%0,%1,%2,%3};"
        : "+f"(c[0]), "+f"(c[1]), "+f"(c[2]), "+f"(c[3])
        : "r"(a[0]), "r"(a[1]), "r"(a[2]), "r"(a[3]), "r"(b[0]), "r"(b[1]));
}

// ---------------------------------------------------------------------------
// Kernel P: prep (measured 10.7us).
//   [0,512): dec_proj partials (b x 16 k-chunks of 64); [512,768): W1_e^T.
// ---------------------------------------------------------------------------
__global__ void __launch_bounds__(256) prep_kernel(
    const float* __restrict__ W1, const float* __restrict__ dh) {
    int bid = blockIdx.x, tid = threadIdx.x;
    if (bid >= 512) {
        __shared__ float tile[32][33];
        int v = bid - 512;
        int d0 = (v & 15) * 32, k0 = (v >> 4) * 32;
        int tx = tid & 31, ty = tid >> 5;
#pragma unroll
        for (int j = 0; j < 32; j += 8)
            tile[ty + j][tx] = W1[(size_t)(1024 + k0 + ty + j) * 512 + d0 + tx];
        __syncthreads();
#pragma unroll
        for (int j = 0; j < 32; j += 8)
            g_W1Tb[(size_t)(d0 + ty + j) * 512 + k0 + tx] = __float2bfloat16_rn(tile[tx][ty + j]);
    } else {
        __shared__ float sdf[64];
        int b = bid >> 4, kc = bid & 15;
        int k0 = kc * 64;
        if (tid < 64) sdf[tid] = dh[b * 1024 + k0 + tid];
        __syncthreads();
        const float* w0 = W1 + (size_t)k0 * 512 + tid;
        const float* w1 = w0 + 256;
        float a[4] = {0.f, 0.f, 0.f, 0.f};
#pragma unroll 4
        for (int k = 0; k < 64; k += 2) {
            a[0] = fmaf(sdf[k],     w0[(size_t)k * 512],       a[0]);
            a[1] = fmaf(sdf[k + 1], w0[(size_t)(k + 1) * 512], a[1]);
            a[2] = fmaf(sdf[k],     w1[(size_t)k * 512],       a[2]);
            a[3] = fmaf(sdf[k + 1], w1[(size_t)(k + 1) * 512], a[3]);
        }
        g_dpp[(size_t)bid * 512 + tid]       = a[0] + a[1];
        g_dpp[(size_t)bid * 512 + tid + 256] = a[2] + a[3];
    }
}

// ---------------------------------------------------------------------------
// Kernel M: R7 staged-convert GEMM (measured ~106us).
// Grid 2048: bid = rc*4 + cu (cu inner -> fp32 A L2-resident).
// Unit 128x128, 8 warps (2m x 4n), warp tile 64x32, occ 2.
// smem: aux 4KB | A32 fp32 32KB (single) | A16 bf16 16KB (single) | B 2x16KB.
// ---------------------------------------------------------------------------
static constexpr uint32_t AUX_SZ  = 4096;
static constexpr uint32_t OFF_A32 = AUX_SZ;            // 32 KB
static constexpr uint32_t OFF_A16 = OFF_A32 + 32768;   // 16 KB
static constexpr uint32_t OFF_B   = OFF_A16 + 16384;   // 2 x 16 KB
static constexpr uint32_t SMEM_MAIN = OFF_B + 32768;   // 86016 (84 KB)

__global__ void __launch_bounds__(256, 2)
attn_main_kernel(const float* __restrict__ enc, const float* __restrict__ b1,
                 const float* __restrict__ w2) {
    extern __shared__ char sm[];
    float* add_s = (float*)sm;                 // 128 f
    float* w2_s  = (float*)(sm + 512);         // 128 f
    float* spart = (float*)(sm + 1024);        // 4 x 128 f
    const uint32_t smu   = smem_u32(sm);
    const uint32_t a32u  = smu + OFF_A32;
    const uint32_t a16u  = smu + OFF_A16;
    const uint32_t bu    = smu + OFF_B;

    const int tid  = threadIdx.x;
    const int lane = tid & 31, wid = tid >> 5;
    const int wm   = wid & 1, wn = wid >> 1;   // 2m x 4n warp grid
    const int quad = lane >> 2, qlane = lane & 3;
    const int lane7 = lane & 7;

    const int cu = blockIdx.x & 3;             // column unit (inner -> L2 A reuse)
    const int rc = blockIdx.x >> 2;            // row chunk 0..511
    const size_t row0 = (size_t)rc * 128;
    const float* gA = enc + row0 * 512;        // fp32 A, converted in-kernel
    const __nv_bfloat16* gB = g_W1Tb + (size_t)(cu * 128) * 512;
    const int b = rc >> 4;

    // add_s = sum of 16 dec_proj partials + b1; w2_s
    if (tid < 128) {
        int d = cu * 128 + tid;
        float s0 = 0.f, s1 = 0.f, s2 = 0.f, s3 = 0.f;
#pragma unroll
        for (int kc = 0; kc < 16; kc += 4) {
            s0 += g_dpp[(size_t)(b * 16 + kc + 0) * 512 + d];
            s1 += g_dpp[(size_t)(b * 16 + kc + 1) * 512 + d];
            s2 += g_dpp[(size_t)(b * 16 + kc + 2) * 512 + d];
            s3 += g_dpp[(size_t)(b * 16 + kc + 3) * 512 + d];
        }
        add_s[tid] = (s0 + s1) + (s2 + s3) + b1[d];
        w2_s[tid]  = w2[d];
    }

    // prefetch fp32 A k-chunk t (128 rows x 64 fp32 = 32KB, linear layout)
    auto prefetchA = [&](int t) {
        const float* src = gA + t * 64;
#pragma unroll
        for (int p = 0; p < 8; p++) {
            int slot = tid + p * 256;          // 2048 chunks of 16B
            int r = slot >> 4, c = slot & 15;
            cp_async16(a32u + (uint32_t)slot * 16, src + (size_t)r * 512 + c * 4);
        }
    };
    // prefetch bf16 B k-chunk t (128 rows x 128B, ldmatrix swizzle), 2 buffers
    auto prefetchB = [&](int t) {
        uint32_t dst = bu + (uint32_t)(t & 1) * 16384;
        const __nv_bfloat16* src = gB + t * 64;
#pragma unroll
        for (int p = 0; p < 4; p++) {
            int slot = tid + p * 256;
            int r = slot >> 3, blk = slot & 7;
            cp_async16(dst + (uint32_t)(r * 128 + ((blk ^ (r & 7)) << 4)),
                       src + (size_t)r * 512 + blk * 8);
        }
    };

    prefetchA(0); prefetchB(0); CP_COMMIT();

    float acc[4][4][4];
#pragma unroll
    for (int mf = 0; mf < 4; mf++)
#pragma unroll
        for (int nf = 0; nf < 4; nf++)
#pragma unroll
            for (int k = 0; k < 4; k++) acc[mf][nf][k] = 0.f;

    const uint32_t a_row = (uint32_t)(wm * 64 + ((lane >> 3) & 1) * 8 + lane7);
    const uint32_t b_row = (uint32_t)(wn * 32 + (lane >> 4) * 8 + lane7);
    const int cv_r0 = tid >> 4, cv_c = tid & 15;   // convert mapping

#pragma unroll 1
    for (int i = 0; i < 8; i++) {
        CP_WAIT(0);
        __syncthreads();                        // A32/B landed; prior MMA reads done

        // ---- convert A32 fp32 -> A16 bf16 (ldmatrix SW128 layout) ----
#pragma unroll
        for (int p = 0; p < 8; p++) {
            int r = cv_r0 + p * 16;
            float4 v = *(const float4*)(sm + OFF_A32 + (uint32_t)(r * 256 + cv_c * 16));
            __nv_bfloat162 q0 = __float22bfloat162_rn({v.x, v.y});
            __nv_bfloat162 q1 = __float22bfloat162_rn({v.z, v.w});
            uint2 o;
            o.x = *(uint32_t*)&q0; o.y = *(uint32_t*)&q1;
            uint32_t off = (uint32_t)(r * 128 + (((cv_c >> 1) ^ (r & 7)) << 4) + (cv_c & 1) * 8);
            *(uint2*)(sm + OFF_A16 + off) = o;
        }
        __syncthreads();                        // A16 ready; A32 free to refill

        if (i < 7) { prefetchA(i + 1); prefetchB(i + 1); CP_COMMIT(); }
        else CP_COMMIT();                       // uniform group accounting

        uint32_t sB = bu + (uint32_t)(i & 1) * 16384;
#pragma unroll
        for (int kf = 0; kf < 4; kf++) {
            uint32_t afr[4][4], bfr[4][2];
            uint32_t ablk = (uint32_t)(((kf * 2 + (lane >> 4)) ^ lane7) << 4);
            uint32_t bblk = (uint32_t)(((kf * 2 + ((lane >> 3) & 1)) ^ lane7) << 4);
#pragma unroll
            for (int mf = 0; mf < 4; mf++)
                ldmatrix_x4(afr[mf], a16u + (a_row + mf * 16) * 128 + ablk);
#pragma unroll
            for (int j = 0; j < 2; j++) {
                uint32_t r[4];
                ldmatrix_x4(r, sB + (b_row + j * 16) * 128 + bblk);
                bfr[2 * j][0] = r[0];     bfr[2 * j][1] = r[1];
                bfr[2 * j + 1][0] = r[2]; bfr[2 * j + 1][1] = r[3];
            }
#pragma unroll
            for (int mf = 0; mf < 4; mf++)
#pragma unroll
                for (int nf = 0; nf < 4; nf++)
                    mma_bf16(acc[mf][nf], afr[mf], bfr[nf]);
        }
    }

    // ---- epilogue: tanh(acc + add) * w2, reduce over this cu's 128 cols ----
#pragma unroll
    for (int mf = 0; mf < 4; mf++) {
        float s0 = 0.f, s1 = 0.f;
#pragma unroll
        for (int nf = 0; nf < 4; nf++) {
            int c = wn * 32 + nf * 8 + qlane * 2;
            float a0 = add_s[c], a1 = add_s[c + 1];
            float v0 = w2_s[c],  v1 = w2_s[c + 1];
            s0 = fmaf(tanh_fast(acc[mf][nf][0] + a0), v0, s0);
            s0 = fmaf(tanh_fast(acc[mf][nf][1] + a1), v1, s0);
            s1 = fmaf(tanh_fast(acc[mf][nf][2] + a0), v0, s1);
            s1 = fmaf(tanh_fast(acc[mf][nf][3] + a1), v1, s1);
        }
        s0 += __shfl_xor_sync(0xffffffffu, s0, 1);
        s0 += __shfl_xor_sync(0xffffffffu, s0, 2);
        s1 += __shfl_xor_sync(0xffffffffu, s1, 1);
        s1 += __shfl_xor_sync(0xffffffffu, s1, 2);
        if (qlane == 0) {
            int r = wm * 64 + mf * 16 + quad;
            spart[wn * 128 + r]     = s0;
            spart[wn * 128 + r + 8] = s1;
        }
    }
    __syncthreads();
    if (tid < 128)
        g_spart[(size_t)cu * 65536 + row0 + tid] =
            spart[tid] + spart[128 + tid] + spart[256 + tid] + spart[384 + tid];
}

// ---------------------------------------------------------------------------
// Kernel S: sum 4 partials + row softmax over 2048. 32 blocks x 256 threads.
// ---------------------------------------------------------------------------
__global__ void softmax_kernel(float* __restrict__ out) {
    __shared__ float red[256];
    int b = blockIdx.x, t = threadIdx.x;
    float v[8];
    float vmax = -1e30f;
#pragma unroll
    for (int j = 0; j < 8; j++) {
        size_t idx = (size_t)b * 2048 + j * 256 + t;
        v[j] = g_spart[idx] + g_spart[65536 + idx] + g_spart[131072 + idx] + g_spart[196608 + idx];
        vmax = fmaxf(vmax, v[j]);
    }
    red[t] = vmax; __syncthreads();
    for (int s = 128; s > 0; s >>= 1) {
        if (t < s) red[t] = fmaxf(red[t], red[t + s]);
        __syncthreads();
    }
    vmax = red[0]; __syncthreads();
    float sum = 0.f;
#pragma unroll
    for (int j = 0; j < 8; j++) {
        v[j] = __expf(v[j] - vmax);
        sum += v[j];
    }
    red[t] = sum; __syncthreads();
    for (int s = 128; s > 0; s >>= 1) {
        if (t < s) red[t] += red[t + s];
        __syncthreads();
    }
    float inv = 1.0f / red[0];
#pragma unroll
    for (int j = 0; j < 8; j++)
        out[b * 2048 + j * 256 + t] = v[j] * inv;
}

// ---------------------------------------------------------------------------
// kernel_launch — inputs: d_hidden, encoder_outputs, W1, b1, w2
// ---------------------------------------------------------------------------
extern "C" void kernel_launch(void* const* d_in, const int* in_sizes, int n_in,
                              void* d_out, int out_size) {
    const float* dh  = (const float*)d_in[0];  // (32, 2, 512)
    const float* enc = (const float*)d_in[1];  // (32, 2048, 512)
    const float* W1  = (const float*)d_in[2];  // (1536, 512)
    const float* b1  = (const float*)d_in[3];  // (512,)
    const float* w2  = (const float*)d_in[4];  // (512,)
    float* out = (float*)d_out;                // (32, 2048)

    cudaFuncSetAttribute(attn_main_kernel, cudaFuncAttributeMaxDynamicSharedMemorySize,
                         (int)SMEM_MAIN);

    prep_kernel<<<768, 256>>>(W1, dh);
    attn_main_kernel<<<2048, 256, SMEM_MAIN>>>(enc, b1, w2);
    softmax_kernel<<<32, 256>>>(out);
}

// round 11
// speedup vs baseline: 1.7123x; 1.0396x over previous
#include <cuda_runtime.h>
#include <cuda_bf16.h>
#include <cstdint>

// ============================================================================
// scores[b,l] = sum_d tanh( (enc[b,l,:] @ W1_e)[d] + dec_proj[b,d] + b1[d] ) * w2[d]
// out = softmax(scores, axis=-1).  B=32, LIN=2048, E=D=512, nd=1024.
//
// R11: split main GEMM.
//   attn_conv_kernel (512 CTAs, cu=0): R10 staged-convert GEMM + STG of the
//     converted bf16 tiles (swizzled layout) into g_encb. Conversion hidden
//     under cu0's GEMM.
//   attn_fast_kernel (1536 CTAs, cu=1..3): R6's measured-79us pure-bf16 loop;
//     A cp.async is a straight copy of the pre-swizzled tiles.
// Kernel boundary = producer/consumer sync. No flags, no caching (g_encb is
// rewritten every launch), deterministic.
// ============================================================================

__device__ __align__(16) __nv_bfloat16 g_W1Tb[512 * 512];   // W1_e^T bf16 [d][k]
__device__ __align__(16) float g_dpp[512 * 512];            // dec_proj partials
__device__ __align__(16) float g_spart[4u * 65536u];        // per-colunit partial scores
__device__ __align__(16) char  g_encb[512u * 131072u];      // 64MB: [rc][kt][16KB swizzled bf16 tile]

// ---------------------------------------------------------------------------
// helpers
// ---------------------------------------------------------------------------
__device__ __forceinline__ uint32_t smem_u32(const void* p) {
    uint32_t a;
    asm("{ .reg .u64 t; cvta.to.shared.u64 t, %1; cvt.u32.u64 %0, t; }" : "=r"(a) : "l"(p));
    return a;
}
__device__ __forceinline__ void cp_async16(uint32_t sdst, const void* gsrc) {
    asm volatile("cp.async.cg.shared.global [%0], [%1], 16;" :: "r"(sdst), "l"(gsrc) : "memory");
}
#define CP_COMMIT() asm volatile("cp.async.commit_group;" ::: "memory")
#define CP_WAIT(n)  asm volatile("cp.async.wait_group %0;" :: "n"(n) : "memory")

__device__ __forceinline__ float tanh_fast(float x) {
    float t;
    asm("tanh.approx.f32 %0, %1;" : "=f"(t) : "f"(x));
    return t;
}
__device__ __forceinline__ void ldmatrix_x4(uint32_t r[4], uint32_t addr) {
    asm volatile("ldmatrix.sync.aligned.m8n8.x4.shared.b16 {%0,%1,%2,%3}, [%4];"
                 : "=r"(r[0]), "=r"(r[1]), "=r"(r[2]), "=r"(r[3]) : "r"(addr));
}
__device__ __forceinline__ void mma_bf16(float c[4], const uint32_t a[4], const uint32_t b[2]) {
    asm volatile(
        "mma.sync.aligned.m16n8k16.row.col.f32.bf16.bf16.f32 "
        "{%0,%1,%2,%3}, {%4,%5,%6,%7}, {%8,%9}, {%0,%1,%2,%3};"
        : "+f"(c[0]), "+f"(c[1]), "+f"(c[2]), "+f"(c[3])
        : "r"(a[0]), "r"(a[1]), "r"(a[2]), "r"(a[3]), "r"(b[0]), "r"(b[1]));
}

// ---------------------------------------------------------------------------
// Kernel P: prep (measured 10.3us).
//   [0,512): dec_proj partials (b x 16 k-chunks of 64); [512,768): W1_e^T.
// ---------------------------------------------------------------------------
__global__ void __launch_bounds__(256) prep_kernel(
    const float* __restrict__ W1, const float* __restrict__ dh) {
    int bid = blockIdx.x, tid = threadIdx.x;
    if (bid >= 512) {
        __shared__ float tile[32][33];
        int v = bid - 512;
        int d0 = (v & 15) * 32, k0 = (v >> 4) * 32;
        int tx = tid & 31, ty = tid >> 5;
#pragma unroll
        for (int j = 0; j < 32; j += 8)
            tile[ty + j][tx] = W1[(size_t)(1024 + k0 + ty + j) * 512 + d0 + tx];
        __syncthreads();
#pragma unroll
        for (int j = 0; j < 32; j += 8)
            g_W1Tb[(size_t)(d0 + ty + j) * 512 + k0 + tx] = __float2bfloat16_rn(tile[tx][ty + j]);
    } else {
        __shared__ float sdf[64];
        int b = bid >> 4, kc = bid & 15;
        int k0 = kc * 64;
        if (tid < 64) sdf[tid] = dh[b * 1024 + k0 + tid];
        __syncthreads();
        const float* w0 = W1 + (size_t)k0 * 512 + tid;
        const float* w1 = w0 + 256;
        float a[4] = {0.f, 0.f, 0.f, 0.f};
#pragma unroll 4
        for (int k = 0; k < 64; k += 2) {
            a[0] = fmaf(sdf[k],     w0[(size_t)k * 512],       a[0]);
            a[1] = fmaf(sdf[k + 1], w0[(size_t)(k + 1) * 512], a[1]);
            a[2] = fmaf(sdf[k],     w1[(size_t)k * 512],       a[2]);
            a[3] = fmaf(sdf[k + 1], w1[(size_t)(k + 1) * 512], a[3]);
        }
        g_dpp[(size_t)bid * 512 + tid]       = a[0] + a[1];
        g_dpp[(size_t)bid * 512 + tid + 256] = a[2] + a[3];
    }
}

// ---------------------------------------------------------------------------
// Kernel C: converter GEMM (cu=0). Grid 512 (one per row chunk), occ 2.
// R10 staged-convert loop + STG of converted bf16 tiles into g_encb.
// smem: aux 4KB | A32 32KB | A16 16KB | B 2x16KB = 84KB.
// ---------------------------------------------------------------------------
static constexpr uint32_t AUX_SZ   = 4096;
static constexpr uint32_t C_OFF_A32 = AUX_SZ;
static constexpr uint32_t C_OFF_A16 = C_OFF_A32 + 32768;
static constexpr uint32_t C_OFF_B   = C_OFF_A16 + 16384;
static constexpr uint32_t SMEM_CONV = C_OFF_B + 32768;   // 86016

__global__ void __launch_bounds__(256, 2)
attn_conv_kernel(const float* __restrict__ enc, const float* __restrict__ b1,
                 const float* __restrict__ w2) {
    extern __shared__ char sm[];
    float* add_s = (float*)sm;
    float* w2_s  = (float*)(sm + 512);
    float* spart = (float*)(sm + 1024);
    const uint32_t smu  = smem_u32(sm);
    const uint32_t a32u = smu + C_OFF_A32;
    const uint32_t a16u = smu + C_OFF_A16;
    const uint32_t bu   = smu + C_OFF_B;

    const int tid  = threadIdx.x;
    const int lane = tid & 31, wid = tid >> 5;
    const int wm   = wid & 1, wn = wid >> 1;
    const int quad = lane >> 2, qlane = lane & 3;
    const int lane7 = lane & 7;

    const int rc = blockIdx.x;                 // 0..511
    const size_t row0 = (size_t)rc * 128;
    const float* gA = enc + row0 * 512;
    const __nv_bfloat16* gB = g_W1Tb;          // cu = 0 -> cols 0..127
    const int b = rc >> 4;

    if (tid < 128) {
        int d = tid;                           // cu*128 + tid, cu=0
        float s0 = 0.f, s1 = 0.f, s2 = 0.f, s3 = 0.f;
#pragma unroll
        for (int kc = 0; kc < 16; kc += 4) {
            s0 += g_dpp[(size_t)(b * 16 + kc + 0) * 512 + d];
            s1 += g_dpp[(size_t)(b * 16 + kc + 1) * 512 + d];
            s2 += g_dpp[(size_t)(b * 16 + kc + 2) * 512 + d];
            s3 += g_dpp[(size_t)(b * 16 + kc + 3) * 512 + d];
        }
        add_s[tid] = (s0 + s1) + (s2 + s3) + b1[d];
        w2_s[tid]  = w2[d];
    }

    auto prefetchA = [&](int t) {
        const float* src = gA + t * 64;
#pragma unroll
        for (int p = 0; p < 8; p++) {
            int slot = tid + p * 256;
            int r = slot >> 4, c = slot & 15;
            cp_async16(a32u + (uint32_t)slot * 16, src + (size_t)r * 512 + c * 4);
        }
    };
    auto prefetchB = [&](int t) {
        uint32_t dst = bu + (uint32_t)(t & 1) * 16384;
        const __nv_bfloat16* src = gB + t * 64;
#pragma unroll
        for (int p = 0; p < 4; p++) {
            int slot = tid + p * 256;
            int r = slot >> 3, blk = slot & 7;
            cp_async16(dst + (uint32_t)(r * 128 + ((blk ^ (r & 7)) << 4)),
                       src + (size_t)r * 512 + blk * 8);
        }
    };

    prefetchA(0); prefetchB(0); CP_COMMIT();

    float acc[4][4][4];
#pragma unroll
    for (int mf = 0; mf < 4; mf++)
#pragma unroll
        for (int nf = 0; nf < 4; nf++)
#pragma unroll
            for (int k = 0; k < 4; k++) acc[mf][nf][k] = 0.f;

    const uint32_t a_row = (uint32_t)(wm * 64 + ((lane >> 3) & 1) * 8 + lane7);
    const uint32_t b_row = (uint32_t)(wn * 32 + (lane >> 4) * 8 + lane7);
    const int cv_r0 = tid >> 4, cv_c = tid & 15;
    char* genc_rc = g_encb + (size_t)rc * 131072;

#pragma unroll 1
    for (int i = 0; i < 8; i++) {
        CP_WAIT(0);
        __syncthreads();

        // convert A32 -> A16 (swizzled) and mirror to g_encb
        char* gdst = genc_rc + (size_t)i * 16384;
#pragma unroll
        for (int p = 0; p < 8; p++) {
            int r = cv_r0 + p * 16;
            float4 v = *(const float4*)(sm + C_OFF_A32 + (uint32_t)(r * 256 + cv_c * 16));
            __nv_bfloat162 q0 = __float22bfloat162_rn({v.x, v.y});
            __nv_bfloat162 q1 = __float22bfloat162_rn({v.z, v.w});
            uint2 o;
            o.x = *(uint32_t*)&q0; o.y = *(uint32_t*)&q1;
            uint32_t off = (uint32_t)(r * 128 + (((cv_c >> 1) ^ (r & 7)) << 4) + (cv_c & 1) * 8);
            *(uint2*)(sm + C_OFF_A16 + off) = o;
            *(uint2*)(gdst + off) = o;
        }
        __syncthreads();

        if (i < 7) { prefetchA(i + 1); prefetchB(i + 1); CP_COMMIT(); }
        else CP_COMMIT();

        uint32_t sB = bu + (uint32_t)(i & 1) * 16384;
#pragma unroll
        for (int kf = 0; kf < 4; kf++) {
            uint32_t afr[4][4], bfr[4][2];
            uint32_t ablk = (uint32_t)(((kf * 2 + (lane >> 4)) ^ lane7) << 4);
            uint32_t bblk = (uint32_t)(((kf * 2 + ((lane >> 3) & 1)) ^ lane7) << 4);
#pragma unroll
            for (int mf = 0; mf < 4; mf++)
                ldmatrix_x4(afr[mf], a16u + (a_row + mf * 16) * 128 + ablk);
#pragma unroll
            for (int j = 0; j < 2; j++) {
                uint32_t r[4];
                ldmatrix_x4(r, sB + (b_row + j * 16) * 128 + bblk);
                bfr[2 * j][0] = r[0];     bfr[2 * j][1] = r[1];
                bfr[2 * j + 1][0] = r[2]; bfr[2 * j + 1][1] = r[3];
            }
#pragma unroll
            for (int mf = 0; mf < 4; mf++)
#pragma unroll
                for (int nf = 0; nf < 4; nf++)
                    mma_bf16(acc[mf][nf], afr[mf], bfr[nf]);
        }
    }

    // epilogue (cu = 0)
#pragma unroll
    for (int mf = 0; mf < 4; mf++) {
        float s0 = 0.f, s1 = 0.f;
#pragma unroll
        for (int nf = 0; nf < 4; nf++) {
            int c = wn * 32 + nf * 8 + qlane * 2;
            float a0 = add_s[c], a1 = add_s[c + 1];
            float v0 = w2_s[c],  v1 = w2_s[c + 1];
            s0 = fmaf(tanh_fast(acc[mf][nf][0] + a0), v0, s0);
            s0 = fmaf(tanh_fast(acc[mf][nf][1] + a1), v1, s0);
            s1 = fmaf(tanh_fast(acc[mf][nf][2] + a0), v0, s1);
            s1 = fmaf(tanh_fast(acc[mf][nf][3] + a1), v1, s1);
        }
        s0 += __shfl_xor_sync(0xffffffffu, s0, 1);
        s0 += __shfl_xor_sync(0xffffffffu, s0, 2);
        s1 += __shfl_xor_sync(0xffffffffu, s1, 1);
        s1 += __shfl_xor_sync(0xffffffffu, s1, 2);
        if (qlane == 0) {
            int r = wm * 64 + mf * 16 + quad;
            spart[wn * 128 + r]     = s0;
            spart[wn * 128 + r + 8] = s1;
        }
    }
    __syncthreads();
    if (tid < 128)
        g_spart[row0 + tid] =
            spart[tid] + spart[128 + tid] + spart[256 + tid] + spart[384 + tid];
}

// ---------------------------------------------------------------------------
// Kernel F: fast GEMM (cu=1..3). Grid 1536: cu = 1 + (bid>>9), rc = bid&511.
// R6 3-stage loop; A cp.async = straight copy of pre-swizzled g_encb tiles.
// smem: aux 4KB | A16 3x16KB | B 3x16KB = 100KB, occ 2.
// ---------------------------------------------------------------------------
static constexpr uint32_t F_OFF_A16 = AUX_SZ;
static constexpr uint32_t F_OFF_B   = F_OFF_A16 + 49152;
static constexpr uint32_t SMEM_FAST = F_OFF_B + 49152;   // 102400

__global__ void __launch_bounds__(256, 2)
attn_fast_kernel(const float* __restrict__ b1, const float* __restrict__ w2) {
    extern __shared__ char sm[];
    float* add_s = (float*)sm;
    float* w2_s  = (float*)(sm + 512);
    float* spart = (float*)(sm + 1024);
    const uint32_t smu  = smem_u32(sm);
    const uint32_t a16u = smu + F_OFF_A16;
    const uint32_t bu   = smu + F_OFF_B;

    const int tid  = threadIdx.x;
    const int lane = tid & 31, wid = tid >> 5;
    const int wm   = wid & 1, wn = wid >> 1;
    const int quad = lane >> 2, qlane = lane & 3;
    const int lane7 = lane & 7;

    const int cu = 1 + (blockIdx.x >> 9);      // 1..3 (cu-outer: B slice L2-hot)
    const int rc = blockIdx.x & 511;
    const size_t row0 = (size_t)rc * 128;
    const char* gA = g_encb + (size_t)rc * 131072;   // pre-swizzled bf16 tiles
    const __nv_bfloat16* gB = g_W1Tb + (size_t)(cu * 128) * 512;
    const int b = rc >> 4;

    if (tid < 128) {
        int d = cu * 128 + tid;
        float s0 = 0.f, s1 = 0.f, s2 = 0.f, s3 = 0.f;
#pragma unroll
        for (int kc = 0; kc < 16; kc += 4) {
            s0 += g_dpp[(size_t)(b * 16 + kc + 0) * 512 + d];
            s1 += g_dpp[(size_t)(b * 16 + kc + 1) * 512 + d];
            s2 += g_dpp[(size_t)(b * 16 + kc + 2) * 512 + d];
            s3 += g_dpp[(size_t)(b * 16 + kc + 3) * 512 + d];
        }
        add_s[tid] = (s0 + s1) + (s2 + s3) + b1[d];
        w2_s[tid]  = w2[d];
    }

    auto prefetch = [&](int t) {
        uint32_t sA = a16u + (uint32_t)(t % 3) * 16384;
        uint32_t sB = bu + (uint32_t)(t % 3) * 16384;
        const char* srcA = gA + (size_t)t * 16384;
        const __nv_bfloat16* srcB = gB + t * 64;
#pragma unroll
        for (int p = 0; p < 4; p++) {
            int slot = tid + p * 256;
            cp_async16(sA + (uint32_t)slot * 16, srcA + (size_t)slot * 16); // layout-preserving
            int r = slot >> 3, blk = slot & 7;
            cp_async16(sB + (uint32_t)(r * 128 + ((blk ^ (r & 7)) << 4)),
                       srcB + (size_t)r * 512 + blk * 8);
        }
        CP_COMMIT();
    };

    prefetch(0); prefetch(1);

    float acc[4][4][4];
#pragma unroll
    for (int mf = 0; mf < 4; mf++)
#pragma unroll
        for (int nf = 0; nf < 4; nf++)
#pragma unroll
            for (int k = 0; k < 4; k++) acc[mf][nf][k] = 0.f;

    const uint32_t a_row = (uint32_t)(wm * 64 + ((lane >> 3) & 1) * 8 + lane7);
    const uint32_t b_row = (uint32_t)(wn * 32 + (lane >> 4) * 8 + lane7);

#pragma unroll 1
    for (int i = 0; i < 8; i++) {
        CP_WAIT(1);
        __syncthreads();
        uint32_t sA = a16u + (uint32_t)(i % 3) * 16384;
        uint32_t sB = bu + (uint32_t)(i % 3) * 16384;

#pragma unroll
        for (int kf = 0; kf < 4; kf++) {
            uint32_t afr[4][4], bfr[4][2];
            uint32_t ablk = (uint32_t)(((kf * 2 + (lane >> 4)) ^ lane7) << 4);
            uint32_t bblk = (uint32_t)(((kf * 2 + ((lane >> 3) & 1)) ^ lane7) << 4);
#pragma unroll
            for (int mf = 0; mf < 4; mf++)
                ldmatrix_x4(afr[mf], sA + (a_row + mf * 16) * 128 + ablk);
#pragma unroll
            for (int j = 0; j < 2; j++) {
                uint32_t r[4];
                ldmatrix_x4(r, sB + (b_row + j * 16) * 128 + bblk);
                bfr[2 * j][0] = r[0];     bfr[2 * j][1] = r[1];
                bfr[2 * j + 1][0] = r[2]; bfr[2 * j + 1][1] = r[3];
            }
#pragma unroll
            for (int mf = 0; mf < 4; mf++)
#pragma unroll
                for (int nf = 0; nf < 4; nf++)
                    mma_bf16(acc[mf][nf], afr[mf], bfr[nf]);
        }

        if (i + 2 < 8) prefetch(i + 2);
        else CP_COMMIT();
    }
    CP_WAIT(0);

    // epilogue
#pragma unroll
    for (int mf = 0; mf < 4; mf++) {
        float s0 = 0.f, s1 = 0.f;
#pragma unroll
        for (int nf = 0; nf < 4; nf++) {
            int c = wn * 32 + nf * 8 + qlane * 2;
            float a0 = add_s[c], a1 = add_s[c + 1];
            float v0 = w2_s[c],  v1 = w2_s[c + 1];
            s0 = fmaf(tanh_fast(acc[mf][nf][0] + a0), v0, s0);
            s0 = fmaf(tanh_fast(acc[mf][nf][1] + a1), v1, s0);
            s1 = fmaf(tanh_fast(acc[mf][nf][2] + a0), v0, s1);
            s1 = fmaf(tanh_fast(acc[mf][nf][3] + a1), v1, s1);
        }
        s0 += __shfl_xor_sync(0xffffffffu, s0, 1);
        s0 += __shfl_xor_sync(0xffffffffu, s0, 2);
        s1 += __shfl_xor_sync(0xffffffffu, s1, 1);
        s1 += __shfl_xor_sync(0xffffffffu, s1, 2);
        if (qlane == 0) {
            int r = wm * 64 + mf * 16 + quad;
            spart[wn * 128 + r]     = s0;
            spart[wn * 128 + r + 8] = s1;
        }
    }
    __syncthreads();
    if (tid < 128)
        g_spart[(size_t)cu * 65536 + row0 + tid] =
            spart[tid] + spart[128 + tid] + spart[256 + tid] + spart[384 + tid];
}

// ---------------------------------------------------------------------------
// Kernel S: sum 4 partials + row softmax over 2048. 32 blocks x 256 threads.
// ---------------------------------------------------------------------------
__global__ void softmax_kernel(float* __restrict__ out) {
    __shared__ float red[256];
    int b = blockIdx.x, t = threadIdx.x;
    float v[8];
    float vmax = -1e30f;
#pragma unroll
    for (int j = 0; j < 8; j++) {
        size_t idx = (size_t)b * 2048 + j * 256 + t;
        v[j] = g_spart[idx] + g_spart[65536 + idx] + g_spart[131072 + idx] + g_spart[196608 + idx];
        vmax = fmaxf(vmax, v[j]);
    }
    red[t] = vmax; __syncthreads();
    for (int s = 128; s > 0; s >>= 1) {
        if (t < s) red[t] = fmaxf(red[t], red[t + s]);
        __syncthreads();
    }
    vmax = red[0]; __syncthreads();
    float sum = 0.f;
#pragma unroll
    for (int j = 0; j < 8; j++) {
        v[j] = __expf(v[j] - vmax);
        sum += v[j];
    }
    red[t] = sum; __syncthreads();
    for (int s = 128; s > 0; s >>= 1) {
        if (t < s) red[t] += red[t + s];
        __syncthreads();
    }
    float inv = 1.0f / red[0];
#pragma unroll
    for (int j = 0; j < 8; j++)
        out[b * 2048 + j * 256 + t] = v[j] * inv;
}

// ---------------------------------------------------------------------------
// kernel_launch — inputs: d_hidden, encoder_outputs, W1, b1, w2
// ---------------------------------------------------------------------------
extern "C" void kernel_launch(void* const* d_in, const int* in_sizes, int n_in,
                              void* d_out, int out_size) {
    const float* dh  = (const float*)d_in[0];  // (32, 2, 512)
    const float* enc = (const float*)d_in[1];  // (32, 2048, 512)
    const float* W1  = (const float*)d_in[2];  // (1536, 512)
    const float* b1  = (const float*)d_in[3];  // (512,)
    const float* w2  = (const float*)d_in[4];  // (512,)
    float* out = (float*)d_out;                // (32, 2048)

    cudaFuncSetAttribute(attn_conv_kernel, cudaFuncAttributeMaxDynamicSharedMemorySize,
                         (int)SMEM_CONV);
    cudaFuncSetAttribute(attn_fast_kernel, cudaFuncAttributeMaxDynamicSharedMemorySize,
                         (int)SMEM_FAST);

    prep_kernel<<<768, 256>>>(W1, dh);
    attn_conv_kernel<<<512, 256, SMEM_CONV>>>(enc, b1, w2);
    attn_fast_kernel<<<1536, 256, SMEM_FAST>>>(b1, w2);
    softmax_kernel<<<32, 256>>>(out);
}